// round 4
// baseline (speedup 1.0000x reference)
#include <cuda_runtime.h>
#include <cuda_bf16.h>
#include <cstdint>

// Problem constants
#define B_   4
#define S_   2048
#define EMB_ 1024
#define H_   16
#define DH_  64
#define M_   (B_ * S_)          // 8192 rows

// Scratch (module-static device memory; no cudaMalloc anywhere)
__device__ float g_Q[B_ * H_ * S_ * DH_];   // [bh][s][d]
__device__ float g_K[B_ * H_ * S_ * DH_];
__device__ float g_V[B_ * H_ * S_ * DH_];
__device__ float g_ctx[M_ * EMB_];          // [b*s][emb]

// ---------------------------------------------------------------------------
// Kernel 1: fused QKV projection.  out[bh][s][d] = x @ W + b  (scatter layout)
// 128x128 block tile, BK=16, 256 threads, 8x8 per-thread micro-tile.
// ---------------------------------------------------------------------------
__global__ __launch_bounds__(256) void qkv_kernel(
    const float* __restrict__ x,
    const float* __restrict__ Wq, const float* __restrict__ bq,
    const float* __restrict__ Wk, const float* __restrict__ bk,
    const float* __restrict__ Wv, const float* __restrict__ bv)
{
    const int z = blockIdx.z;
    const float* W    = (z == 0) ? Wq : (z == 1) ? Wk : Wv;
    const float* bias = (z == 0) ? bq : (z == 1) ? bk : bv;
    float* out        = (z == 0) ? g_Q : (z == 1) ? g_K : g_V;

    __shared__ float As[16][128];   // transposed A tile
    __shared__ float Bs[16][128];

    const int tid = threadIdx.x;
    const int m0  = blockIdx.y * 128;
    const int n0  = blockIdx.x * 128;
    const int ty  = tid >> 4;       // 0..15
    const int tx  = tid & 15;       // 0..15

    float acc[8][8];
#pragma unroll
    for (int i = 0; i < 8; i++)
#pragma unroll
        for (int j = 0; j < 8; j++) acc[i][j] = 0.f;

    for (int k0 = 0; k0 < EMB_; k0 += 16) {
        // load A tile 128x16 (transposed into As)
#pragma unroll
        for (int q = 0; q < 2; q++) {
            int v   = tid + 256 * q;       // 0..511
            int row = v >> 2;              // 0..127
            int c4  = v & 3;               // 0..3
            float4 a = *(const float4*)&x[(size_t)(m0 + row) * EMB_ + k0 + c4 * 4];
            As[c4 * 4 + 0][row] = a.x;
            As[c4 * 4 + 1][row] = a.y;
            As[c4 * 4 + 2][row] = a.z;
            As[c4 * 4 + 3][row] = a.w;
        }
        // load B tile 16x128
#pragma unroll
        for (int q = 0; q < 2; q++) {
            int v   = tid + 256 * q;
            int row = v >> 5;              // 0..15
            int c4  = v & 31;              // 0..31
            *(float4*)&Bs[row][c4 * 4] =
                *(const float4*)&W[(size_t)(k0 + row) * EMB_ + n0 + c4 * 4];
        }
        __syncthreads();

#pragma unroll
        for (int k = 0; k < 16; k++) {
            float ra[8], rb[8];
            *(float4*)&ra[0] = *(float4*)&As[k][ty * 8];
            *(float4*)&ra[4] = *(float4*)&As[k][ty * 8 + 4];
            *(float4*)&rb[0] = *(float4*)&Bs[k][tx * 8];
            *(float4*)&rb[4] = *(float4*)&Bs[k][tx * 8 + 4];
#pragma unroll
            for (int i = 0; i < 8; i++)
#pragma unroll
                for (int j = 0; j < 8; j++)
                    acc[i][j] += ra[i] * rb[j];
        }
        __syncthreads();
    }

    // epilogue: add bias, scatter to [bh][s][d]
#pragma unroll
    for (int i = 0; i < 8; i++) {
        int m = m0 + ty * 8 + i;
        int b = m >> 11;            // /2048
        int s = m & 2047;
#pragma unroll
        for (int j4 = 0; j4 < 2; j4++) {
            int n = n0 + tx * 8 + j4 * 4;
            int h = n >> 6;
            int d = n & 63;
            float4 o;
            o.x = acc[i][j4 * 4 + 0] + bias[n + 0];
            o.y = acc[i][j4 * 4 + 1] + bias[n + 1];
            o.z = acc[i][j4 * 4 + 2] + bias[n + 2];
            o.w = acc[i][j4 * 4 + 3] + bias[n + 3];
            *(float4*)&out[((size_t)(b * H_ + h) * S_ + s) * DH_ + d] = o;
        }
    }
}

// ---------------------------------------------------------------------------
// Kernel 2: flash attention.  grid = (S/64, B*H), 256 threads.
// 64 queries per block, 32-key tiles, online softmax.
// Thread map: r = tid&63 (query row), cg = tid>>6 (16-wide d / 8-wide key slice).
// Warp = 32 consecutive r, constant cg  -> K/V smem reads are warp-uniform.
// ---------------------------------------------------------------------------
__global__ __launch_bounds__(256) void attn_kernel()
{
    __shared__ float Qs[64][68];
    __shared__ float Ks[32][68];
    __shared__ float Vs[32][68];
    __shared__ float Ps[64][33];
    __shared__ float redmax[4][64];
    __shared__ float redsum[4][64];

    const int tid = threadIdx.x;
    const int r   = tid & 63;
    const int cg  = tid >> 6;
    const int bh  = blockIdx.y;
    const int q0  = blockIdx.x * 64;

    const float* Qg = g_Q + ((size_t)bh * S_ + q0) * DH_;
    const float* Kg = g_K + (size_t)bh * S_ * DH_;
    const float* Vg = g_V + (size_t)bh * S_ * DH_;

    // load Q tile (pre-scaled by 1/sqrt(Dh))
#pragma unroll
    for (int q = 0; q < 4; q++) {
        int v   = tid + 256 * q;   // 0..1023
        int row = v >> 4;          // 0..63
        int c4  = v & 15;
        float4 a = *(const float4*)&Qg[row * DH_ + c4 * 4];
        a.x *= 0.125f; a.y *= 0.125f; a.z *= 0.125f; a.w *= 0.125f;
        *(float4*)&Qs[row][c4 * 4] = a;
    }

    float O[16];
#pragma unroll
    for (int j = 0; j < 16; j++) O[j] = 0.f;
    float m_run = -1e30f, l_run = 0.f;

    for (int kt = 0; kt < S_ / 32; kt++) {
        const float* Kt = Kg + (size_t)kt * 32 * DH_;
        const float* Vt = Vg + (size_t)kt * 32 * DH_;
        __syncthreads();   // protect Ks/Vs/Ps from previous iteration
#pragma unroll
        for (int q = 0; q < 2; q++) {
            int v   = tid + 256 * q;  // 0..511
            int row = v >> 4;         // 0..31
            int c4  = v & 15;
            *(float4*)&Ks[row][c4 * 4] = *(const float4*)&Kt[row * DH_ + c4 * 4];
            *(float4*)&Vs[row][c4 * 4] = *(const float4*)&Vt[row * DH_ + c4 * 4];
        }
        __syncthreads();

        // S = Q K^T for keys cg*8 .. cg*8+7 (this thread's row r)
        float sacc[8];
#pragma unroll
        for (int j = 0; j < 8; j++) sacc[j] = 0.f;
#pragma unroll
        for (int d4 = 0; d4 < 16; d4++) {
            float4 qv = *(float4*)&Qs[r][d4 * 4];
#pragma unroll
            for (int j = 0; j < 8; j++) {
                float4 kv = *(float4*)&Ks[cg * 8 + j][d4 * 4];
                sacc[j] += qv.x * kv.x + qv.y * kv.y + qv.z * kv.z + qv.w * kv.w;
            }
        }

        // row max (partial across the 4 cg threads of this row)
        float pmax = sacc[0];
#pragma unroll
        for (int j = 1; j < 8; j++) pmax = fmaxf(pmax, sacc[j]);
        redmax[cg][r] = pmax;
        __syncthreads();

        float mt    = fmaxf(fmaxf(redmax[0][r], redmax[1][r]),
                            fmaxf(redmax[2][r], redmax[3][r]));
        float m_new = fmaxf(m_run, mt);
        float scale = __expf(m_run - m_new);
        m_run = m_new;

        float psum = 0.f;
#pragma unroll
        for (int j = 0; j < 8; j++) {
            float p = __expf(sacc[j] - m_new);
            psum += p;
            Ps[r][cg * 8 + j] = p;
        }
        redsum[cg][r] = psum;
#pragma unroll
        for (int j = 0; j < 16; j++) O[j] *= scale;
        __syncthreads();

        l_run = l_run * scale +
                redsum[0][r] + redsum[1][r] + redsum[2][r] + redsum[3][r];

        // O += P V  (this thread's 16 d-columns: cg*16 .. cg*16+15)
#pragma unroll
        for (int k = 0; k < 32; k++) {
            float p = Ps[r][k];
            float4 v0 = *(float4*)&Vs[k][cg * 16 + 0];
            float4 v1 = *(float4*)&Vs[k][cg * 16 + 4];
            float4 v2 = *(float4*)&Vs[k][cg * 16 + 8];
            float4 v3 = *(float4*)&Vs[k][cg * 16 + 12];
            O[0]  += p * v0.x; O[1]  += p * v0.y; O[2]  += p * v0.z; O[3]  += p * v0.w;
            O[4]  += p * v1.x; O[5]  += p * v1.y; O[6]  += p * v1.z; O[7]  += p * v1.w;
            O[8]  += p * v2.x; O[9]  += p * v2.y; O[10] += p * v2.z; O[11] += p * v2.w;
            O[12] += p * v3.x; O[13] += p * v3.y; O[14] += p * v3.z; O[15] += p * v3.w;
        }
    }

    // epilogue: normalize and write ctx in [B,S,EMB] layout
    float inv = 1.f / l_run;
    int b = bh >> 4;
    int h = bh & 15;
    float* outp = g_ctx + ((size_t)(b * S_) + q0 + r) * EMB_ + h * DH_ + cg * 16;
#pragma unroll
    for (int j4 = 0; j4 < 4; j4++) {
        float4 o;
        o.x = O[j4 * 4 + 0] * inv;
        o.y = O[j4 * 4 + 1] * inv;
        o.z = O[j4 * 4 + 2] * inv;
        o.w = O[j4 * 4 + 3] * inv;
        *(float4*)&outp[j4 * 4] = o;
    }
}

// ---------------------------------------------------------------------------
// Kernel 3: output projection.  out = ctx @ Wo + bo   (plain sgemm)
// ---------------------------------------------------------------------------
__global__ __launch_bounds__(256) void out_gemm_kernel(
    const float* __restrict__ W, const float* __restrict__ bias,
    float* __restrict__ out)
{
    __shared__ float As[16][128];
    __shared__ float Bs[16][128];

    const float* A = g_ctx;
    const int tid = threadIdx.x;
    const int m0  = blockIdx.y * 128;
    const int n0  = blockIdx.x * 128;
    const int ty  = tid >> 4;
    const int tx  = tid & 15;

    float acc[8][8];
#pragma unroll
    for (int i = 0; i < 8; i++)
#pragma unroll
        for (int j = 0; j < 8; j++) acc[i][j] = 0.f;

    for (int k0 = 0; k0 < EMB_; k0 += 16) {
#pragma unroll
        for (int q = 0; q < 2; q++) {
            int v   = tid + 256 * q;
            int row = v >> 2;
            int c4  = v & 3;
            float4 a = *(const float4*)&A[(size_t)(m0 + row) * EMB_ + k0 + c4 * 4];
            As[c4 * 4 + 0][row] = a.x;
            As[c4 * 4 + 1][row] = a.y;
            As[c4 * 4 + 2][row] = a.z;
            As[c4 * 4 + 3][row] = a.w;
        }
#pragma unroll
        for (int q = 0; q < 2; q++) {
            int v   = tid + 256 * q;
            int row = v >> 5;
            int c4  = v & 31;
            *(float4*)&Bs[row][c4 * 4] =
                *(const float4*)&W[(size_t)(k0 + row) * EMB_ + n0 + c4 * 4];
        }
        __syncthreads();

#pragma unroll
        for (int k = 0; k < 16; k++) {
            float ra[8], rb[8];
            *(float4*)&ra[0] = *(float4*)&As[k][ty * 8];
            *(float4*)&ra[4] = *(float4*)&As[k][ty * 8 + 4];
            *(float4*)&rb[0] = *(float4*)&Bs[k][tx * 8];
            *(float4*)&rb[4] = *(float4*)&Bs[k][tx * 8 + 4];
#pragma unroll
            for (int i = 0; i < 8; i++)
#pragma unroll
                for (int j = 0; j < 8; j++)
                    acc[i][j] += ra[i] * rb[j];
        }
        __syncthreads();
    }

#pragma unroll
    for (int i = 0; i < 8; i++) {
        int m = m0 + ty * 8 + i;
#pragma unroll
        for (int j4 = 0; j4 < 2; j4++) {
            int n = n0 + tx * 8 + j4 * 4;
            float4 o;
            o.x = acc[i][j4 * 4 + 0] + bias[n + 0];
            o.y = acc[i][j4 * 4 + 1] + bias[n + 1];
            o.z = acc[i][j4 * 4 + 2] + bias[n + 2];
            o.w = acc[i][j4 * 4 + 3] + bias[n + 3];
            *(float4*)&out[(size_t)m * EMB_ + n] = o;
        }
    }
}

// ---------------------------------------------------------------------------
// Launch
// ---------------------------------------------------------------------------
extern "C" void kernel_launch(void* const* d_in, const int* in_sizes, int n_in,
                              void* d_out, int out_size)
{
    const float* x  = (const float*)d_in[0];
    const float* Wq = (const float*)d_in[1];
    const float* bq = (const float*)d_in[2];
    const float* Wk = (const float*)d_in[3];
    const float* bk = (const float*)d_in[4];
    const float* Wv = (const float*)d_in[5];
    const float* bv = (const float*)d_in[6];
    const float* Wo = (const float*)d_in[7];
    const float* bo = (const float*)d_in[8];
    float* out = (float*)d_out;

    dim3 gQKV(EMB_ / 128, M_ / 128, 3);           // (8, 64, 3)
    qkv_kernel<<<gQKV, 256>>>(x, Wq, bq, Wk, bk, Wv, bv);

    dim3 gAttn(S_ / 64, B_ * H_);                 // (32, 64)
    attn_kernel<<<gAttn, 256>>>();

    dim3 gO(EMB_ / 128, M_ / 128);                // (8, 64)
    out_gemm_kernel<<<gO, 256>>>(Wo, bo, out);
}

// round 7
// speedup vs baseline: 1.3682x; 1.3682x over previous
#include <cuda_runtime.h>
#include <cstdint>

// Problem constants
#define B_   4
#define S_   2048
#define EMB_ 1024
#define H_   16
#define DH_  64
#define M_   (B_ * S_)          // 8192 rows

typedef unsigned long long u64t;

// Scratch (module-static device memory; no cudaMalloc anywhere)
__device__ float g_Q[B_ * H_ * S_ * DH_];   // [bh][s][d]
__device__ float g_K[B_ * H_ * S_ * DH_];
__device__ float g_V[B_ * H_ * S_ * DH_];
__device__ float g_ctx[M_ * EMB_];          // [b*s][emb]

// ---------------------------------------------------------------------------
// Helpers
// ---------------------------------------------------------------------------
__device__ __forceinline__ uint32_t tf32r(float f) {
    uint32_t u;
    asm("cvt.rna.tf32.f32 %0, %1;" : "=r"(u) : "f"(f));
    return u;
}

__device__ __forceinline__ void mma_tf32(float* c, const uint32_t* a,
                                         uint32_t b0, uint32_t b1) {
    asm volatile(
        "mma.sync.aligned.m16n8k8.row.col.f32.tf32.tf32.f32 "
        "{%0,%1,%2,%3}, {%4,%5,%6,%7}, {%8,%9}, {%0,%1,%2,%3};"
        : "+f"(c[0]), "+f"(c[1]), "+f"(c[2]), "+f"(c[3])
        : "r"(a[0]), "r"(a[1]), "r"(a[2]), "r"(a[3]), "r"(b0), "r"(b1));
}

// f32x2 packed math (base sm_100-family ISA, not 'a'-gated)
__device__ __forceinline__ u64t ffma2(u64t a, u64t b, u64t c) {
    u64t d; asm("fma.rn.f32x2 %0, %1, %2, %3;" : "=l"(d) : "l"(a), "l"(b), "l"(c)); return d;
}
__device__ __forceinline__ u64t fmul2(u64t a, u64t b) {
    u64t d; asm("mul.rn.f32x2 %0, %1, %2;" : "=l"(d) : "l"(a), "l"(b)); return d;
}
__device__ __forceinline__ u64t pk2(float x, float y) {
    u64t d; asm("mov.b64 %0, {%1, %2};" : "=l"(d) : "f"(x), "f"(y)); return d;
}
__device__ __forceinline__ float2 upk2(u64t a) {
    float2 f; asm("mov.b64 {%0, %1}, %2;" : "=f"(f.x), "=f"(f.y) : "l"(a)); return f;
}

// ---------------------------------------------------------------------------
// tf32 mma.sync GEMM body:  out[m,n] = sum_k A[m,k] * W[k,n] + bias[n]
// CTA tile 128x128, BK=32, 256 threads = 8 warps (4m x 2n), warp tile 32x64.
// scatter=1: write to [bh][s][d] layout (QKV).  scatter=0: row-major out.
// ---------------------------------------------------------------------------
__device__ __forceinline__ void gemm_mma_body(
    const float* __restrict__ A, const float* __restrict__ W,
    const float* __restrict__ bias, float* __restrict__ out, int scatter)
{
    __shared__ uint32_t As[128][36];   // [m][k], pad->conflict-free frags
    __shared__ uint32_t Bs[32][132];   // [k][n]

    const int tid  = threadIdx.x;
    const int lane = tid & 31;
    const int wid  = tid >> 5;
    const int wm   = wid & 3;          // warp m index (0..3)
    const int wn   = wid >> 2;         // warp n index (0..1)
    const int m0   = blockIdx.y * 128;
    const int n0   = blockIdx.x * 128;
    const int gm   = wm * 32;
    const int gn   = wn * 64;
    const int row4 = lane >> 2;        // 0..7
    const int kq   = lane & 3;         // 0..3

    float acc[2][8][4];
#pragma unroll
    for (int mt = 0; mt < 2; mt++)
#pragma unroll
        for (int nt = 0; nt < 8; nt++)
#pragma unroll
            for (int i = 0; i < 4; i++) acc[mt][nt][i] = 0.f;

    // per-thread loader offsets
    size_t aoff[4], boff[4];
    uint32_t* sA[4];
    uint32_t* sB[4];
#pragma unroll
    for (int i = 0; i < 4; i++) {
        int v = tid + 256 * i;
        int ar = v >> 3, ak = v & 7;       // A: 128 rows x 8 float4
        int br = v >> 5, bn = v & 31;      // B: 32 rows x 32 float4
        aoff[i] = (size_t)(m0 + ar) * EMB_ + ak * 4;
        boff[i] = (size_t)br * EMB_ + n0 + bn * 4;
        sA[i] = &As[ar][ak * 4];
        sB[i] = &Bs[br][bn * 4];
    }

    // prefetch first phase
    float4 pa[4], pb[4];
#pragma unroll
    for (int i = 0; i < 4; i++) {
        pa[i] = *(const float4*)(A + aoff[i]);
        pb[i] = *(const float4*)(W + boff[i]);
    }

#pragma unroll 1
    for (int c = 0; c < 32; c++) {
        if (c > 0) __syncthreads();   // protect smem from previous compute
#pragma unroll
        for (int i = 0; i < 4; i++) {
            uint4 ua;
            ua.x = tf32r(pa[i].x); ua.y = tf32r(pa[i].y);
            ua.z = tf32r(pa[i].z); ua.w = tf32r(pa[i].w);
            *(uint4*)sA[i] = ua;
            uint4 ub;
            ub.x = tf32r(pb[i].x); ub.y = tf32r(pb[i].y);
            ub.z = tf32r(pb[i].z); ub.w = tf32r(pb[i].w);
            *(uint4*)sB[i] = ub;
        }
        __syncthreads();

        if (c < 31) {   // prefetch next phase (overlaps with mma below)
            size_t ka = (size_t)(c + 1) * 32;
#pragma unroll
            for (int i = 0; i < 4; i++) {
                pa[i] = *(const float4*)(A + aoff[i] + ka);
                pb[i] = *(const float4*)(W + boff[i] + ka * EMB_);
            }
        }

#pragma unroll
        for (int s = 0; s < 4; s++) {
            const int kk = s * 8;
            uint32_t a[2][4];
#pragma unroll
            for (int mt = 0; mt < 2; mt++) {
                a[mt][0] = As[gm + mt * 16 + row4][kk + kq];
                a[mt][1] = As[gm + mt * 16 + row4 + 8][kk + kq];
                a[mt][2] = As[gm + mt * 16 + row4][kk + kq + 4];
                a[mt][3] = As[gm + mt * 16 + row4 + 8][kk + kq + 4];
            }
#pragma unroll
            for (int nt = 0; nt < 8; nt++) {
                uint32_t b0 = Bs[kk + kq][gn + nt * 8 + row4];
                uint32_t b1 = Bs[kk + kq + 4][gn + nt * 8 + row4];
                mma_tf32(acc[0][nt], a[0], b0, b1);
                mma_tf32(acc[1][nt], a[1], b0, b1);
            }
        }
    }

    // epilogue
#pragma unroll
    for (int mt = 0; mt < 2; mt++) {
        int r0 = m0 + gm + mt * 16 + row4;     // rows r0 and r0+8
#pragma unroll
        for (int nt = 0; nt < 8; nt++) {
            int cc = n0 + gn + nt * 8 + 2 * kq;
            float2 v0, v1;
            v0.x = acc[mt][nt][0] + bias[cc];
            v0.y = acc[mt][nt][1] + bias[cc + 1];
            v1.x = acc[mt][nt][2] + bias[cc];
            v1.y = acc[mt][nt][3] + bias[cc + 1];
            if (scatter) {
                int h = cc >> 6, d = cc & 63;
                int b0r = r0 >> 11, s0 = r0 & 2047;
                int b1r = (r0 + 8) >> 11, s1 = (r0 + 8) & 2047;
                *(float2*)(out + ((size_t)(b0r * H_ + h) * S_ + s0) * DH_ + d) = v0;
                *(float2*)(out + ((size_t)(b1r * H_ + h) * S_ + s1) * DH_ + d) = v1;
            } else {
                *(float2*)(out + (size_t)r0 * EMB_ + cc) = v0;
                *(float2*)(out + (size_t)(r0 + 8) * EMB_ + cc) = v1;
            }
        }
    }
}

__global__ __launch_bounds__(256, 2) void qkv_mma_kernel(
    const float* __restrict__ x,
    const float* __restrict__ Wq, const float* __restrict__ bq,
    const float* __restrict__ Wk, const float* __restrict__ bk,
    const float* __restrict__ Wv, const float* __restrict__ bv)
{
    const int z = blockIdx.z;
    const float* W    = (z == 0) ? Wq : (z == 1) ? Wk : Wv;
    const float* bias = (z == 0) ? bq : (z == 1) ? bk : bv;
    float* out        = (z == 0) ? g_Q : (z == 1) ? g_K : g_V;
    gemm_mma_body(x, W, bias, out, 1);
}

__global__ __launch_bounds__(256, 2) void oproj_mma_kernel(
    const float* __restrict__ Wo, const float* __restrict__ bo,
    float* __restrict__ out)
{
    gemm_mma_body(g_ctx, Wo, bo, out, 0);
}

// ---------------------------------------------------------------------------
// Flash attention with packed f32x2 FMA.  grid = (S/64, B*H), 256 threads.
// ---------------------------------------------------------------------------
__global__ __launch_bounds__(256) void attn_kernel()
{
    __shared__ float Qs[64][68];
    __shared__ float Ks[32][68];
    __shared__ float Vs[32][68];
    __shared__ float Ps[64][33];
    __shared__ float redmax[4][64];
    __shared__ float redsum[4][64];

    const int tid = threadIdx.x;
    const int r   = tid & 63;
    const int cg  = tid >> 6;
    const int bh  = blockIdx.y;
    const int q0  = blockIdx.x * 64;

    const float* Qg = g_Q + ((size_t)bh * S_ + q0) * DH_;
    const float* Kg = g_K + (size_t)bh * S_ * DH_;
    const float* Vg = g_V + (size_t)bh * S_ * DH_;

    // load Q tile (pre-scaled by 1/sqrt(Dh))
#pragma unroll
    for (int q = 0; q < 4; q++) {
        int v   = tid + 256 * q;
        int row = v >> 4;
        int c4  = v & 15;
        float4 a = *(const float4*)&Qg[row * DH_ + c4 * 4];
        a.x *= 0.125f; a.y *= 0.125f; a.z *= 0.125f; a.w *= 0.125f;
        *(float4*)&Qs[row][c4 * 4] = a;
    }

    u64t O2[8];
#pragma unroll
    for (int j = 0; j < 8; j++) O2[j] = 0ull;
    float m_run = -1e30f, l_run = 0.f;

    for (int kt = 0; kt < S_ / 32; kt++) {
        const float* Kt = Kg + (size_t)kt * 32 * DH_;
        const float* Vt = Vg + (size_t)kt * 32 * DH_;
        __syncthreads();
#pragma unroll
        for (int q = 0; q < 2; q++) {
            int v   = tid + 256 * q;
            int row = v >> 4;
            int c4  = v & 15;
            *(float4*)&Ks[row][c4 * 4] = *(const float4*)&Kt[row * DH_ + c4 * 4];
            *(float4*)&Vs[row][c4 * 4] = *(const float4*)&Vt[row * DH_ + c4 * 4];
        }
        __syncthreads();

        // S = Q K^T for keys cg*8 .. cg*8+7  (packed f32x2)
        u64t s2[8];
#pragma unroll
        for (int j = 0; j < 8; j++) s2[j] = 0ull;
#pragma unroll
        for (int d4 = 0; d4 < 16; d4++) {
            float4 qv = *(float4*)&Qs[r][d4 * 4];
            u64t q01 = pk2(qv.x, qv.y), q23 = pk2(qv.z, qv.w);
#pragma unroll
            for (int j = 0; j < 8; j++) {
                float4 kv = *(float4*)&Ks[cg * 8 + j][d4 * 4];
                s2[j] = ffma2(q01, pk2(kv.x, kv.y), s2[j]);
                s2[j] = ffma2(q23, pk2(kv.z, kv.w), s2[j]);
            }
        }
        float sacc[8];
#pragma unroll
        for (int j = 0; j < 8; j++) {
            float2 f = upk2(s2[j]);
            sacc[j] = f.x + f.y;
        }

        // row max across the 4 cg threads of this row
        float pmax = sacc[0];
#pragma unroll
        for (int j = 1; j < 8; j++) pmax = fmaxf(pmax, sacc[j]);
        redmax[cg][r] = pmax;
        __syncthreads();

        float mt    = fmaxf(fmaxf(redmax[0][r], redmax[1][r]),
                            fmaxf(redmax[2][r], redmax[3][r]));
        float m_new = fmaxf(m_run, mt);
        float scale = __expf(m_run - m_new);
        m_run = m_new;

        float psum = 0.f;
#pragma unroll
        for (int j = 0; j < 8; j++) {
            float p = __expf(sacc[j] - m_new);
            psum += p;
            Ps[r][cg * 8 + j] = p;
        }
        redsum[cg][r] = psum;

        u64t sc2 = pk2(scale, scale);
#pragma unroll
        for (int j = 0; j < 8; j++) O2[j] = fmul2(O2[j], sc2);
        __syncthreads();

        l_run = l_run * scale +
                redsum[0][r] + redsum[1][r] + redsum[2][r] + redsum[3][r];

        // O += P V   (16 d-columns per thread, packed as 8 f32x2)
#pragma unroll
        for (int k = 0; k < 32; k++) {
            float p = Ps[r][k];
            u64t p2 = pk2(p, p);
            float4 v0 = *(float4*)&Vs[k][cg * 16 + 0];
            float4 v1 = *(float4*)&Vs[k][cg * 16 + 4];
            float4 v2 = *(float4*)&Vs[k][cg * 16 + 8];
            float4 v3 = *(float4*)&Vs[k][cg * 16 + 12];
            O2[0] = ffma2(p2, pk2(v0.x, v0.y), O2[0]);
            O2[1] = ffma2(p2, pk2(v0.z, v0.w), O2[1]);
            O2[2] = ffma2(p2, pk2(v1.x, v1.y), O2[2]);
            O2[3] = ffma2(p2, pk2(v1.z, v1.w), O2[3]);
            O2[4] = ffma2(p2, pk2(v2.x, v2.y), O2[4]);
            O2[5] = ffma2(p2, pk2(v2.z, v2.w), O2[5]);
            O2[6] = ffma2(p2, pk2(v3.x, v3.y), O2[6]);
            O2[7] = ffma2(p2, pk2(v3.z, v3.w), O2[7]);
        }
    }

    // epilogue: normalize and write ctx in [B,S,EMB] layout
    float inv = 1.f / l_run;
    int b = bh >> 4;
    int h = bh & 15;
    float* outp = g_ctx + ((size_t)(b * S_) + q0 + r) * EMB_ + h * DH_ + cg * 16;
#pragma unroll
    for (int j2 = 0; j2 < 4; j2++) {
        float2 a = upk2(O2[j2 * 2 + 0]);
        float2 c = upk2(O2[j2 * 2 + 1]);
        float4 o;
        o.x = a.x * inv; o.y = a.y * inv;
        o.z = c.x * inv; o.w = c.y * inv;
        *(float4*)&outp[j2 * 4] = o;
    }
}

// ---------------------------------------------------------------------------
// Launch
// ---------------------------------------------------------------------------
extern "C" void kernel_launch(void* const* d_in, const int* in_sizes, int n_in,
                              void* d_out, int out_size)
{
    const float* x  = (const float*)d_in[0];
    const float* Wq = (const float*)d_in[1];
    const float* bq = (const float*)d_in[2];
    const float* Wk = (const float*)d_in[3];
    const float* bk = (const float*)d_in[4];
    const float* Wv = (const float*)d_in[5];
    const float* bv = (const float*)d_in[6];
    const float* Wo = (const float*)d_in[7];
    const float* bo = (const float*)d_in[8];
    float* out = (float*)d_out;

    dim3 gQKV(EMB_ / 128, M_ / 128, 3);           // (8, 64, 3)
    qkv_mma_kernel<<<gQKV, 256>>>(x, Wq, bq, Wk, bk, Wv, bv);

    dim3 gAttn(S_ / 64, B_ * H_);                 // (32, 64)
    attn_kernel<<<gAttn, 256>>>();

    dim3 gO(EMB_ / 128, M_ / 128);                // (8, 64)
    oproj_mma_kernel<<<gO, 256>>>(Wo, bo, out);
}

// round 9
// speedup vs baseline: 3.0338x; 2.2173x over previous
#include <cuda_runtime.h>
#include <cstdint>

// Problem constants
#define B_   4
#define S_   2048
#define EMB_ 1024
#define H_   16
#define DH_  64
#define M_   (B_ * S_)          // 8192 rows

// Scratch (module-static device memory; no cudaMalloc anywhere)
__device__ float g_Q[B_ * H_ * S_ * DH_];   // [bh][s][d]
__device__ float g_K[B_ * H_ * S_ * DH_];
__device__ float g_V[B_ * H_ * S_ * DH_];
__device__ float g_ctx[M_ * EMB_];          // [b*s][emb]

// ---------------------------------------------------------------------------
// Helpers
// ---------------------------------------------------------------------------
__device__ __forceinline__ uint32_t tf32r(float f) {
    uint32_t u;
    asm("cvt.rna.tf32.f32 %0, %1;" : "=r"(u) : "f"(f));
    return u;
}

__device__ __forceinline__ void mma_tf32(float* c, const uint32_t* a,
                                         uint32_t b0, uint32_t b1) {
    asm volatile(
        "mma.sync.aligned.m16n8k8.row.col.f32.tf32.tf32.f32 "
        "{%0,%1,%2,%3}, {%4,%5,%6,%7}, {%8,%9}, {%0,%1,%2,%3};"
        : "+f"(c[0]), "+f"(c[1]), "+f"(c[2]), "+f"(c[3])
        : "r"(a[0]), "r"(a[1]), "r"(a[2]), "r"(a[3]), "r"(b0), "r"(b1));
}

// ---------------------------------------------------------------------------
// tf32 mma.sync GEMM body (unchanged from R6 — verified):
// out[m,n] = sum_k A[m,k] * W[k,n] + bias[n]
// CTA tile 128x128, BK=32, 256 threads = 8 warps (4m x 2n), warp tile 32x64.
// ---------------------------------------------------------------------------
__device__ __forceinline__ void gemm_mma_body(
    const float* __restrict__ A, const float* __restrict__ W,
    const float* __restrict__ bias, float* __restrict__ out, int scatter)
{
    __shared__ uint32_t As[128][36];   // [m][k]
    __shared__ uint32_t Bs[32][132];   // [k][n]

    const int tid  = threadIdx.x;
    const int lane = tid & 31;
    const int wid  = tid >> 5;
    const int wm   = wid & 3;
    const int wn   = wid >> 2;
    const int m0   = blockIdx.y * 128;
    const int n0   = blockIdx.x * 128;
    const int gm   = wm * 32;
    const int gn   = wn * 64;
    const int row4 = lane >> 2;
    const int kq   = lane & 3;

    float acc[2][8][4];
#pragma unroll
    for (int mt = 0; mt < 2; mt++)
#pragma unroll
        for (int nt = 0; nt < 8; nt++)
#pragma unroll
            for (int i = 0; i < 4; i++) acc[mt][nt][i] = 0.f;

    size_t aoff[4], boff[4];
    uint32_t* sA[4];
    uint32_t* sB[4];
#pragma unroll
    for (int i = 0; i < 4; i++) {
        int v = tid + 256 * i;
        int ar = v >> 3, ak = v & 7;
        int br = v >> 5, bn = v & 31;
        aoff[i] = (size_t)(m0 + ar) * EMB_ + ak * 4;
        boff[i] = (size_t)br * EMB_ + n0 + bn * 4;
        sA[i] = &As[ar][ak * 4];
        sB[i] = &Bs[br][bn * 4];
    }

    float4 pa[4], pb[4];
#pragma unroll
    for (int i = 0; i < 4; i++) {
        pa[i] = *(const float4*)(A + aoff[i]);
        pb[i] = *(const float4*)(W + boff[i]);
    }

#pragma unroll 1
    for (int c = 0; c < 32; c++) {
        if (c > 0) __syncthreads();
#pragma unroll
        for (int i = 0; i < 4; i++) {
            uint4 ua;
            ua.x = tf32r(pa[i].x); ua.y = tf32r(pa[i].y);
            ua.z = tf32r(pa[i].z); ua.w = tf32r(pa[i].w);
            *(uint4*)sA[i] = ua;
            uint4 ub;
            ub.x = tf32r(pb[i].x); ub.y = tf32r(pb[i].y);
            ub.z = tf32r(pb[i].z); ub.w = tf32r(pb[i].w);
            *(uint4*)sB[i] = ub;
        }
        __syncthreads();

        if (c < 31) {
            size_t ka = (size_t)(c + 1) * 32;
#pragma unroll
            for (int i = 0; i < 4; i++) {
                pa[i] = *(const float4*)(A + aoff[i] + ka);
                pb[i] = *(const float4*)(W + boff[i] + ka * EMB_);
            }
        }

#pragma unroll
        for (int s = 0; s < 4; s++) {
            const int kk = s * 8;
            uint32_t a[2][4];
#pragma unroll
            for (int mt = 0; mt < 2; mt++) {
                a[mt][0] = As[gm + mt * 16 + row4][kk + kq];
                a[mt][1] = As[gm + mt * 16 + row4 + 8][kk + kq];
                a[mt][2] = As[gm + mt * 16 + row4][kk + kq + 4];
                a[mt][3] = As[gm + mt * 16 + row4 + 8][kk + kq + 4];
            }
#pragma unroll
            for (int nt = 0; nt < 8; nt++) {
                uint32_t b0 = Bs[kk + kq][gn + nt * 8 + row4];
                uint32_t b1 = Bs[kk + kq + 4][gn + nt * 8 + row4];
                mma_tf32(acc[0][nt], a[0], b0, b1);
                mma_tf32(acc[1][nt], a[1], b0, b1);
            }
        }
    }

#pragma unroll
    for (int mt = 0; mt < 2; mt++) {
        int r0 = m0 + gm + mt * 16 + row4;
#pragma unroll
        for (int nt = 0; nt < 8; nt++) {
            int cc = n0 + gn + nt * 8 + 2 * kq;
            float2 v0, v1;
            v0.x = acc[mt][nt][0] + bias[cc];
            v0.y = acc[mt][nt][1] + bias[cc + 1];
            v1.x = acc[mt][nt][2] + bias[cc];
            v1.y = acc[mt][nt][3] + bias[cc + 1];
            if (scatter) {
                int h = cc >> 6, d = cc & 63;
                int b0r = r0 >> 11, s0 = r0 & 2047;
                int b1r = (r0 + 8) >> 11, s1 = (r0 + 8) & 2047;
                *(float2*)(out + ((size_t)(b0r * H_ + h) * S_ + s0) * DH_ + d) = v0;
                *(float2*)(out + ((size_t)(b1r * H_ + h) * S_ + s1) * DH_ + d) = v1;
            } else {
                *(float2*)(out + (size_t)r0 * EMB_ + cc) = v0;
                *(float2*)(out + (size_t)(r0 + 8) * EMB_ + cc) = v1;
            }
        }
    }
}

__global__ __launch_bounds__(256, 2) void qkv_mma_kernel(
    const float* __restrict__ x,
    const float* __restrict__ Wq, const float* __restrict__ bq,
    const float* __restrict__ Wk, const float* __restrict__ bk,
    const float* __restrict__ Wv, const float* __restrict__ bv)
{
    const int z = blockIdx.z;
    const float* W    = (z == 0) ? Wq : (z == 1) ? Wk : Wv;
    const float* bias = (z == 0) ? bq : (z == 1) ? bk : bv;
    float* out        = (z == 0) ? g_Q : (z == 1) ? g_K : g_V;
    gemm_mma_body(x, W, bias, out, 1);
}

__global__ __launch_bounds__(256, 2) void oproj_mma_kernel(
    const float* __restrict__ Wo, const float* __restrict__ bo,
    float* __restrict__ out)
{
    gemm_mma_body(g_ctx, Wo, bo, out, 0);
}

// ---------------------------------------------------------------------------
// Flash attention with tf32 mma.sync.
// CTA: 128 queries x one head.  16 iterations over 128-key tiles.
// S = Q K^T: warps 4m x 2n (warp tile 32q x 64k), Q split hi/lo (2 passes).
// PV:        warps 4m x 2n (warp tile 32q x 32d).
// Dynamic smem (u32 units):
//   QHI[128][68], QLO[128][68], KS[128][68], VS[128][68],
//   PS[128][132], RED[4][128] (max lo/hi halves then sum)
// ---------------------------------------------------------------------------
#define O_QHI 0
#define O_QLO 8704
#define O_KS  17408
#define O_VS  26112
#define O_PS  34816
#define O_RED 51712
#define ATTN_SMEM_U32 52224
#define ATTN_SMEM_BYTES (ATTN_SMEM_U32 * 4)

__global__ __launch_bounds__(256, 1) void attn_mma_kernel()
{
    extern __shared__ uint32_t sm[];
    float* smf = (float*)sm;

    const int tid  = threadIdx.x;
    const int lane = tid & 31;
    const int wid  = tid >> 5;
    const int wm   = wid & 3;
    const int wn   = wid >> 2;
    const int row4 = lane >> 2;
    const int kq   = lane & 3;
    const int gm   = wm * 32;
    const int gn   = wn * 64;     // S: key columns
    const int gn2  = wn * 32;     // PV: d columns

    const int bh = blockIdx.y;
    const int q0 = blockIdx.x * 128;

    const float* Qg = g_Q + ((size_t)bh * S_ + q0) * DH_;
    const float* Kg = g_K + (size_t)bh * S_ * DH_;
    const float* Vg = g_V + (size_t)bh * S_ * DH_;

    // ---- load Q tile, build hi/lo tf32 split (pre-scaled by 1/8) ----
#pragma unroll
    for (int i = 0; i < 8; i++) {
        int v   = tid + 256 * i;      // 0..2047
        int row = v >> 4;
        int c4  = v & 15;
        float4 q = *(const float4*)(Qg + row * DH_ + c4 * 4);
        q.x *= 0.125f; q.y *= 0.125f; q.z *= 0.125f; q.w *= 0.125f;
        uint4 hi, lo;
        hi.x = tf32r(q.x); lo.x = tf32r(q.x - __uint_as_float(hi.x));
        hi.y = tf32r(q.y); lo.y = tf32r(q.y - __uint_as_float(hi.y));
        hi.z = tf32r(q.z); lo.z = tf32r(q.z - __uint_as_float(hi.z));
        hi.w = tf32r(q.w); lo.w = tf32r(q.w - __uint_as_float(hi.w));
        *(uint4*)&sm[O_QHI + row * 68 + c4 * 4] = hi;
        *(uint4*)&sm[O_QLO + row * 68 + c4 * 4] = lo;
    }

    float Oa[2][4][4];
#pragma unroll
    for (int mt = 0; mt < 2; mt++)
#pragma unroll
        for (int nt = 0; nt < 4; nt++)
#pragma unroll
            for (int i = 0; i < 4; i++) Oa[mt][nt][i] = 0.f;
    float m_run[2][2] = {{-1e30f, -1e30f}, {-1e30f, -1e30f}};
    float l_run[2][2] = {{0.f, 0.f}, {0.f, 0.f}};

#pragma unroll 1
    for (int kt = 0; kt < S_ / 128; kt++) {
        __syncthreads();   // previous iteration's mma reads of KS/VS/PS done
        const int k0 = kt * 128;
#pragma unroll
        for (int i = 0; i < 8; i++) {
            int v   = tid + 256 * i;
            int row = v >> 4;
            int c4  = v & 15;
            float4 kv = *(const float4*)(Kg + (size_t)(k0 + row) * DH_ + c4 * 4);
            uint4 uk;
            uk.x = tf32r(kv.x); uk.y = tf32r(kv.y);
            uk.z = tf32r(kv.z); uk.w = tf32r(kv.w);
            *(uint4*)&sm[O_KS + row * 68 + c4 * 4] = uk;
            float4 vv = *(const float4*)(Vg + (size_t)(k0 + row) * DH_ + c4 * 4);
            uint4 uv;
            uv.x = tf32r(vv.x); uv.y = tf32r(vv.y);
            uv.z = tf32r(vv.z); uv.w = tf32r(vv.w);
            *(uint4*)&sm[O_VS + row * 68 + c4 * 4] = uv;
        }
        __syncthreads();

        // ---- S = Q K^T  (hi + lo passes) ----
        float acc[2][8][4];
#pragma unroll
        for (int mt = 0; mt < 2; mt++)
#pragma unroll
            for (int nt = 0; nt < 8; nt++)
#pragma unroll
                for (int i = 0; i < 4; i++) acc[mt][nt][i] = 0.f;

#pragma unroll
        for (int s = 0; s < 8; s++) {
            const int kk = s * 8;
            uint32_t ah[2][4], al[2][4];
#pragma unroll
            for (int mt = 0; mt < 2; mt++) {
                int rbase = (gm + mt * 16 + row4) * 68;
                ah[mt][0] = sm[O_QHI + rbase + kk + kq];
                ah[mt][1] = sm[O_QHI + rbase + 8 * 68 + kk + kq];
                ah[mt][2] = sm[O_QHI + rbase + kk + kq + 4];
                ah[mt][3] = sm[O_QHI + rbase + 8 * 68 + kk + kq + 4];
                al[mt][0] = sm[O_QLO + rbase + kk + kq];
                al[mt][1] = sm[O_QLO + rbase + 8 * 68 + kk + kq];
                al[mt][2] = sm[O_QLO + rbase + kk + kq + 4];
                al[mt][3] = sm[O_QLO + rbase + 8 * 68 + kk + kq + 4];
            }
#pragma unroll
            for (int nt = 0; nt < 8; nt++) {
                int nb = (gn + nt * 8 + row4) * 68;
                uint32_t b0 = sm[O_KS + nb + kk + kq];
                uint32_t b1 = sm[O_KS + nb + kk + kq + 4];
                mma_tf32(acc[0][nt], ah[0], b0, b1);
                mma_tf32(acc[1][nt], ah[1], b0, b1);
                mma_tf32(acc[0][nt], al[0], b0, b1);
                mma_tf32(acc[1][nt], al[1], b0, b1);
            }
        }

        // ---- online softmax ----
        float rmax[2][2];
#pragma unroll
        for (int mt = 0; mt < 2; mt++) {
            rmax[mt][0] = acc[mt][0][0];
            rmax[mt][1] = acc[mt][0][2];
#pragma unroll
            for (int nt = 0; nt < 8; nt++) {
                rmax[mt][0] = fmaxf(rmax[mt][0], fmaxf(acc[mt][nt][0], acc[mt][nt][1]));
                rmax[mt][1] = fmaxf(rmax[mt][1], fmaxf(acc[mt][nt][2], acc[mt][nt][3]));
            }
#pragma unroll
            for (int h = 0; h < 2; h++) {
                rmax[mt][h] = fmaxf(rmax[mt][h], __shfl_xor_sync(0xffffffffu, rmax[mt][h], 1));
                rmax[mt][h] = fmaxf(rmax[mt][h], __shfl_xor_sync(0xffffffffu, rmax[mt][h], 2));
            }
        }
        if (kq == 0) {
#pragma unroll
            for (int mt = 0; mt < 2; mt++)
#pragma unroll
                for (int h = 0; h < 2; h++)
                    smf[O_RED + wn * 128 + gm + mt * 16 + h * 8 + row4] = rmax[mt][h];
        }
        __syncthreads();

        float scale[2][2];
#pragma unroll
        for (int mt = 0; mt < 2; mt++)
#pragma unroll
            for (int h = 0; h < 2; h++) {
                int r = gm + mt * 16 + h * 8 + row4;
                float mtile = fmaxf(smf[O_RED + r], smf[O_RED + 128 + r]);
                float mnew  = fmaxf(m_run[mt][h], mtile);
                scale[mt][h] = __expf(m_run[mt][h] - mnew);
                m_run[mt][h] = mnew;
            }

        // p = exp(s - m), store tf32 P to smem, accumulate row sums
        float rsum[2][2] = {{0.f, 0.f}, {0.f, 0.f}};
#pragma unroll
        for (int mt = 0; mt < 2; mt++)
#pragma unroll
            for (int nt = 0; nt < 8; nt++) {
                float p0 = __expf(acc[mt][nt][0] - m_run[mt][0]);
                float p1 = __expf(acc[mt][nt][1] - m_run[mt][0]);
                float p2 = __expf(acc[mt][nt][2] - m_run[mt][1]);
                float p3 = __expf(acc[mt][nt][3] - m_run[mt][1]);
                rsum[mt][0] += p0 + p1;
                rsum[mt][1] += p2 + p3;
                int cc = gn + nt * 8 + 2 * kq;
                uint2 u0; u0.x = tf32r(p0); u0.y = tf32r(p1);
                uint2 u1; u1.x = tf32r(p2); u1.y = tf32r(p3);
                *(uint2*)&sm[O_PS + (gm + mt * 16 + row4) * 132 + cc] = u0;
                *(uint2*)&sm[O_PS + (gm + mt * 16 + row4 + 8) * 132 + cc] = u1;
            }
#pragma unroll
        for (int mt = 0; mt < 2; mt++)
#pragma unroll
            for (int h = 0; h < 2; h++) {
                rsum[mt][h] += __shfl_xor_sync(0xffffffffu, rsum[mt][h], 1);
                rsum[mt][h] += __shfl_xor_sync(0xffffffffu, rsum[mt][h], 2);
            }
        if (kq == 0) {
#pragma unroll
            for (int mt = 0; mt < 2; mt++)
#pragma unroll
                for (int h = 0; h < 2; h++)
                    smf[O_RED + 256 + wn * 128 + gm + mt * 16 + h * 8 + row4] = rsum[mt][h];
        }

        // rescale O while sums land
#pragma unroll
        for (int mt = 0; mt < 2; mt++)
#pragma unroll
            for (int nt = 0; nt < 4; nt++) {
                Oa[mt][nt][0] *= scale[mt][0];
                Oa[mt][nt][1] *= scale[mt][0];
                Oa[mt][nt][2] *= scale[mt][1];
                Oa[mt][nt][3] *= scale[mt][1];
            }
        __syncthreads();   // P + redsum visible

#pragma unroll
        for (int mt = 0; mt < 2; mt++)
#pragma unroll
            for (int h = 0; h < 2; h++) {
                int r = gm + mt * 16 + h * 8 + row4;
                l_run[mt][h] = l_run[mt][h] * scale[mt][h]
                             + smf[O_RED + 256 + r] + smf[O_RED + 256 + 128 + r];
            }

        // ---- O += P V ----
#pragma unroll
        for (int s2 = 0; s2 < 16; s2++) {
            const int kk = s2 * 8;
            uint32_t a[2][4];
#pragma unroll
            for (int mt = 0; mt < 2; mt++) {
                int rbase = (gm + mt * 16 + row4) * 132;
                a[mt][0] = sm[O_PS + rbase + kk + kq];
                a[mt][1] = sm[O_PS + rbase + 8 * 132 + kk + kq];
                a[mt][2] = sm[O_PS + rbase + kk + kq + 4];
                a[mt][3] = sm[O_PS + rbase + 8 * 132 + kk + kq + 4];
            }
#pragma unroll
            for (int nt = 0; nt < 4; nt++) {
                int nb = (kk + kq) * 68 + gn2 + nt * 8 + row4;
                uint32_t b0 = sm[O_VS + nb];
                uint32_t b1 = sm[O_VS + nb + 4 * 68];
                mma_tf32(Oa[0][nt], a[0], b0, b1);
                mma_tf32(Oa[1][nt], a[1], b0, b1);
            }
        }
    }

    // ---- epilogue: normalize and write ctx [B,S,EMB] ----
    const int b = bh >> 4;
    const int h = bh & 15;
#pragma unroll
    for (int mt = 0; mt < 2; mt++) {
        float inv0 = 1.f / l_run[mt][0];
        float inv1 = 1.f / l_run[mt][1];
        int r0 = q0 + gm + mt * 16 + row4;
#pragma unroll
        for (int nt = 0; nt < 4; nt++) {
            int d = gn2 + nt * 8 + 2 * kq;
            float2 v0, v1;
            v0.x = Oa[mt][nt][0] * inv0; v0.y = Oa[mt][nt][1] * inv0;
            v1.x = Oa[mt][nt][2] * inv1; v1.y = Oa[mt][nt][3] * inv1;
            *(float2*)(g_ctx + ((size_t)(b * S_) + r0) * EMB_ + h * DH_ + d) = v0;
            *(float2*)(g_ctx + ((size_t)(b * S_) + r0 + 8) * EMB_ + h * DH_ + d) = v1;
        }
    }
}

// ---------------------------------------------------------------------------
// Launch
// ---------------------------------------------------------------------------
extern "C" void kernel_launch(void* const* d_in, const int* in_sizes, int n_in,
                              void* d_out, int out_size)
{
    const float* x  = (const float*)d_in[0];
    const float* Wq = (const float*)d_in[1];
    const float* bq = (const float*)d_in[2];
    const float* Wk = (const float*)d_in[3];
    const float* bk = (const float*)d_in[4];
    const float* Wv = (const float*)d_in[5];
    const float* bv = (const float*)d_in[6];
    const float* Wo = (const float*)d_in[7];
    const float* bo = (const float*)d_in[8];
    float* out = (float*)d_out;

    cudaFuncSetAttribute(attn_mma_kernel,
                         cudaFuncAttributeMaxDynamicSharedMemorySize, ATTN_SMEM_BYTES);

    dim3 gQKV(EMB_ / 128, M_ / 128, 3);           // (8, 64, 3)
    qkv_mma_kernel<<<gQKV, 256>>>(x, Wq, bq, Wk, bk, Wv, bv);

    dim3 gAttn(S_ / 128, B_ * H_);                // (16, 64)
    attn_mma_kernel<<<gAttn, 256, ATTN_SMEM_BYTES>>>();

    dim3 gO(EMB_ / 128, M_ / 128);                // (8, 64)
    oproj_mma_kernel<<<gO, 256>>>(Wo, bo, out);
}

// round 11
// speedup vs baseline: 3.3418x; 1.1015x over previous
#include <cuda_runtime.h>
#include <cstdint>

// Problem constants
#define B_   4
#define S_   2048
#define EMB_ 1024
#define H_   16
#define DH_  64
#define M_   (B_ * S_)          // 8192 rows

// Scratch (module-static device memory; no cudaMalloc anywhere)
__device__ float g_Q[B_ * H_ * S_ * DH_];   // [bh][s][d]
__device__ float g_K[B_ * H_ * S_ * DH_];
__device__ float g_V[B_ * H_ * S_ * DH_];
__device__ float g_ctx[M_ * EMB_];          // [b*s][emb]

// ---------------------------------------------------------------------------
// Helpers
// ---------------------------------------------------------------------------
__device__ __forceinline__ uint32_t tf32r(float f) {
    uint32_t u;
    asm("cvt.rna.tf32.f32 %0, %1;" : "=r"(u) : "f"(f));
    return u;
}

__device__ __forceinline__ void mma_tf32(float* c, const uint32_t* a,
                                         uint32_t b0, uint32_t b1) {
    asm volatile(
        "mma.sync.aligned.m16n8k8.row.col.f32.tf32.tf32.f32 "
        "{%0,%1,%2,%3}, {%4,%5,%6,%7}, {%8,%9}, {%0,%1,%2,%3};"
        : "+f"(c[0]), "+f"(c[1]), "+f"(c[2]), "+f"(c[3])
        : "r"(a[0]), "r"(a[1]), "r"(a[2]), "r"(a[3]), "r"(b0), "r"(b1));
}

// ---------------------------------------------------------------------------
// tf32 mma.sync GEMM body (verified in R6/R8 — unchanged):
// out[m,n] = sum_k A[m,k] * W[k,n] + bias[n]
// CTA tile 128x128, BK=32, 256 threads = 8 warps (4m x 2n), warp tile 32x64.
// ---------------------------------------------------------------------------
__device__ __forceinline__ void gemm_mma_body(
    const float* __restrict__ A, const float* __restrict__ W,
    const float* __restrict__ bias, float* __restrict__ out, int scatter)
{
    __shared__ uint32_t As[128][36];   // [m][k]
    __shared__ uint32_t Bs[32][132];   // [k][n]

    const int tid  = threadIdx.x;
    const int lane = tid & 31;
    const int wid  = tid >> 5;
    const int wm   = wid & 3;
    const int wn   = wid >> 2;
    const int m0   = blockIdx.y * 128;
    const int n0   = blockIdx.x * 128;
    const int gm   = wm * 32;
    const int gn   = wn * 64;
    const int row4 = lane >> 2;
    const int kq   = lane & 3;

    float acc[2][8][4];
#pragma unroll
    for (int mt = 0; mt < 2; mt++)
#pragma unroll
        for (int nt = 0; nt < 8; nt++)
#pragma unroll
            for (int i = 0; i < 4; i++) acc[mt][nt][i] = 0.f;

    size_t aoff[4], boff[4];
    uint32_t* sA[4];
    uint32_t* sB[4];
#pragma unroll
    for (int i = 0; i < 4; i++) {
        int v = tid + 256 * i;
        int ar = v >> 3, ak = v & 7;
        int br = v >> 5, bn = v & 31;
        aoff[i] = (size_t)(m0 + ar) * EMB_ + ak * 4;
        boff[i] = (size_t)br * EMB_ + n0 + bn * 4;
        sA[i] = &As[ar][ak * 4];
        sB[i] = &Bs[br][bn * 4];
    }

    float4 pa[4], pb[4];
#pragma unroll
    for (int i = 0; i < 4; i++) {
        pa[i] = *(const float4*)(A + aoff[i]);
        pb[i] = *(const float4*)(W + boff[i]);
    }

#pragma unroll 1
    for (int c = 0; c < 32; c++) {
        if (c > 0) __syncthreads();
#pragma unroll
        for (int i = 0; i < 4; i++) {
            uint4 ua;
            ua.x = tf32r(pa[i].x); ua.y = tf32r(pa[i].y);
            ua.z = tf32r(pa[i].z); ua.w = tf32r(pa[i].w);
            *(uint4*)sA[i] = ua;
            uint4 ub;
            ub.x = tf32r(pb[i].x); ub.y = tf32r(pb[i].y);
            ub.z = tf32r(pb[i].z); ub.w = tf32r(pb[i].w);
            *(uint4*)sB[i] = ub;
        }
        __syncthreads();

        if (c < 31) {
            size_t ka = (size_t)(c + 1) * 32;
#pragma unroll
            for (int i = 0; i < 4; i++) {
                pa[i] = *(const float4*)(A + aoff[i] + ka);
                pb[i] = *(const float4*)(W + boff[i] + ka * EMB_);
            }
        }

#pragma unroll
        for (int s = 0; s < 4; s++) {
            const int kk = s * 8;
            uint32_t a[2][4];
#pragma unroll
            for (int mt = 0; mt < 2; mt++) {
                a[mt][0] = As[gm + mt * 16 + row4][kk + kq];
                a[mt][1] = As[gm + mt * 16 + row4 + 8][kk + kq];
                a[mt][2] = As[gm + mt * 16 + row4][kk + kq + 4];
                a[mt][3] = As[gm + mt * 16 + row4 + 8][kk + kq + 4];
            }
#pragma unroll
            for (int nt = 0; nt < 8; nt++) {
                uint32_t b0 = Bs[kk + kq][gn + nt * 8 + row4];
                uint32_t b1 = Bs[kk + kq + 4][gn + nt * 8 + row4];
                mma_tf32(acc[0][nt], a[0], b0, b1);
                mma_tf32(acc[1][nt], a[1], b0, b1);
            }
        }
    }

#pragma unroll
    for (int mt = 0; mt < 2; mt++) {
        int r0 = m0 + gm + mt * 16 + row4;
#pragma unroll
        for (int nt = 0; nt < 8; nt++) {
            int cc = n0 + gn + nt * 8 + 2 * kq;
            float2 v0, v1;
            v0.x = acc[mt][nt][0] + bias[cc];
            v0.y = acc[mt][nt][1] + bias[cc + 1];
            v1.x = acc[mt][nt][2] + bias[cc];
            v1.y = acc[mt][nt][3] + bias[cc + 1];
            if (scatter) {
                int h = cc >> 6, d = cc & 63;
                int b0r = r0 >> 11, s0 = r0 & 2047;
                int b1r = (r0 + 8) >> 11, s1 = (r0 + 8) & 2047;
                *(float2*)(out + ((size_t)(b0r * H_ + h) * S_ + s0) * DH_ + d) = v0;
                *(float2*)(out + ((size_t)(b1r * H_ + h) * S_ + s1) * DH_ + d) = v1;
            } else {
                *(float2*)(out + (size_t)r0 * EMB_ + cc) = v0;
                *(float2*)(out + (size_t)(r0 + 8) * EMB_ + cc) = v1;
            }
        }
    }
}

__global__ __launch_bounds__(256, 2) void qkv_mma_kernel(
    const float* __restrict__ x,
    const float* __restrict__ Wq, const float* __restrict__ bq,
    const float* __restrict__ Wk, const float* __restrict__ bk,
    const float* __restrict__ Wv, const float* __restrict__ bv)
{
    const int z = blockIdx.z;
    const float* W    = (z == 0) ? Wq : (z == 1) ? Wk : Wv;
    const float* bias = (z == 0) ? bq : (z == 1) ? bk : bv;
    float* out        = (z == 0) ? g_Q : (z == 1) ? g_K : g_V;
    gemm_mma_body(x, W, bias, out, 1);
}

__global__ __launch_bounds__(256, 2) void oproj_mma_kernel(
    const float* __restrict__ Wo, const float* __restrict__ bo,
    float* __restrict__ out)
{
    gemm_mma_body(g_ctx, Wo, bo, out, 0);
}

// ---------------------------------------------------------------------------
// Flash attention with tf32 mma.sync, v2:
//  * Q single-pass (hi/lo split removed — error budget allows it)
//  * Q and K smem pair-interleaved in k per 8-chunk: (k0,k4,k1,k5,k2,k6,k3,k7)
//    row stride 72 u32 -> conflict-free LDS.64 fragment loads (a: 4, b: 8 per
//    k-step instead of 16+16 scalar).
// CTA: 128 queries x one head, 16 iterations over 128-key tiles.
// S = Q K^T: warps 4m x 2n (warp tile 32q x 64k).
// PV:        warps 4m x 2n (warp tile 32q x 32d).
// Dynamic smem (u32): QS[128][72], KS[128][72], VS[128][68], PS[128][132],
//                     RED[512]
// ---------------------------------------------------------------------------
#define O_QS  0
#define O_KS  9216
#define O_VS  18432
#define O_PS  27136
#define O_RED 44032
#define ATTN_SMEM_U32 44544
#define ATTN_SMEM_BYTES (ATTN_SMEM_U32 * 4)

__global__ __launch_bounds__(256, 1) void attn_mma_kernel()
{
    extern __shared__ uint32_t sm[];
    float* smf = (float*)sm;

    const int tid  = threadIdx.x;
    const int lane = tid & 31;
    const int wid  = tid >> 5;
    const int wm   = wid & 3;
    const int wn   = wid >> 2;
    const int row4 = lane >> 2;
    const int kq   = lane & 3;
    const int gm   = wm * 32;
    const int gn   = wn * 64;     // S: key columns
    const int gn2  = wn * 32;     // PV: d columns

    const int bh = blockIdx.y;
    const int q0 = blockIdx.x * 128;

    const float* Qg = g_Q + ((size_t)bh * S_ + q0) * DH_;
    const float* Kg = g_K + (size_t)bh * S_ * DH_;
    const float* Vg = g_V + (size_t)bh * S_ * DH_;

    // ---- load Q tile: scale by 1/8, tf32, pair-interleave k ----
#pragma unroll
    for (int i = 0; i < 4; i++) {
        int v   = tid + 256 * i;      // 0..1023
        int row = v >> 3;             // 0..127
        int seg = v & 7;              // 8-k segment
        const float* p = Qg + row * DH_ + seg * 8;
        float4 a = *(const float4*)p;
        float4 b = *(const float4*)(p + 4);
        uint4 u0, u1;
        u0.x = tf32r(a.x * 0.125f); u0.y = tf32r(b.x * 0.125f);
        u0.z = tf32r(a.y * 0.125f); u0.w = tf32r(b.y * 0.125f);
        u1.x = tf32r(a.z * 0.125f); u1.y = tf32r(b.z * 0.125f);
        u1.z = tf32r(a.w * 0.125f); u1.w = tf32r(b.w * 0.125f);
        *(uint4*)&sm[O_QS + row * 72 + seg * 8]     = u0;
        *(uint4*)&sm[O_QS + row * 72 + seg * 8 + 4] = u1;
    }

    float Oa[2][4][4];
#pragma unroll
    for (int mt = 0; mt < 2; mt++)
#pragma unroll
        for (int nt = 0; nt < 4; nt++)
#pragma unroll
            for (int i = 0; i < 4; i++) Oa[mt][nt][i] = 0.f;
    float m_run[2][2] = {{-1e30f, -1e30f}, {-1e30f, -1e30f}};
    float l_run[2][2] = {{0.f, 0.f}, {0.f, 0.f}};

#pragma unroll 1
    for (int kt = 0; kt < S_ / 128; kt++) {
        __syncthreads();   // previous iteration's mma reads of KS/VS/PS done
        const int k0 = kt * 128;
        // K: pair-interleaved
#pragma unroll
        for (int i = 0; i < 4; i++) {
            int v   = tid + 256 * i;
            int row = v >> 3;
            int seg = v & 7;
            const float* p = Kg + (size_t)(k0 + row) * DH_ + seg * 8;
            float4 a = *(const float4*)p;
            float4 b = *(const float4*)(p + 4);
            uint4 u0, u1;
            u0.x = tf32r(a.x); u0.y = tf32r(b.x);
            u0.z = tf32r(a.y); u0.w = tf32r(b.y);
            u1.x = tf32r(a.z); u1.y = tf32r(b.z);
            u1.z = tf32r(a.w); u1.w = tf32r(b.w);
            *(uint4*)&sm[O_KS + row * 72 + seg * 8]     = u0;
            *(uint4*)&sm[O_KS + row * 72 + seg * 8 + 4] = u1;
        }
        // V: plain [key][d]
#pragma unroll
        for (int i = 0; i < 8; i++) {
            int v   = tid + 256 * i;
            int row = v >> 4;
            int c4  = v & 15;
            float4 vv = *(const float4*)(Vg + (size_t)(k0 + row) * DH_ + c4 * 4);
            uint4 uv;
            uv.x = tf32r(vv.x); uv.y = tf32r(vv.y);
            uv.z = tf32r(vv.z); uv.w = tf32r(vv.w);
            *(uint4*)&sm[O_VS + row * 68 + c4 * 4] = uv;
        }
        __syncthreads();

        // ---- S = Q K^T (single pass, paired LDS.64 fragments) ----
        float acc[2][8][4];
#pragma unroll
        for (int mt = 0; mt < 2; mt++)
#pragma unroll
            for (int nt = 0; nt < 8; nt++)
#pragma unroll
                for (int i = 0; i < 4; i++) acc[mt][nt][i] = 0.f;

#pragma unroll
        for (int s = 0; s < 8; s++) {
            const int sc = s * 8 + 2 * kq;
            uint32_t a[2][4];
#pragma unroll
            for (int mt = 0; mt < 2; mt++) {
                uint2 qa = *(uint2*)&sm[O_QS + (gm + mt * 16 + row4) * 72 + sc];
                uint2 qb = *(uint2*)&sm[O_QS + (gm + mt * 16 + row4 + 8) * 72 + sc];
                a[mt][0] = qa.x; a[mt][1] = qb.x;
                a[mt][2] = qa.y; a[mt][3] = qb.y;
            }
#pragma unroll
            for (int nt = 0; nt < 8; nt++) {
                uint2 kb = *(uint2*)&sm[O_KS + (gn + nt * 8 + row4) * 72 + sc];
                mma_tf32(acc[0][nt], a[0], kb.x, kb.y);
                mma_tf32(acc[1][nt], a[1], kb.x, kb.y);
            }
        }

        // ---- online softmax ----
        float rmax[2][2];
#pragma unroll
        for (int mt = 0; mt < 2; mt++) {
            rmax[mt][0] = acc[mt][0][0];
            rmax[mt][1] = acc[mt][0][2];
#pragma unroll
            for (int nt = 0; nt < 8; nt++) {
                rmax[mt][0] = fmaxf(rmax[mt][0], fmaxf(acc[mt][nt][0], acc[mt][nt][1]));
                rmax[mt][1] = fmaxf(rmax[mt][1], fmaxf(acc[mt][nt][2], acc[mt][nt][3]));
            }
#pragma unroll
            for (int h = 0; h < 2; h++) {
                rmax[mt][h] = fmaxf(rmax[mt][h], __shfl_xor_sync(0xffffffffu, rmax[mt][h], 1));
                rmax[mt][h] = fmaxf(rmax[mt][h], __shfl_xor_sync(0xffffffffu, rmax[mt][h], 2));
            }
        }
        if (kq == 0) {
#pragma unroll
            for (int mt = 0; mt < 2; mt++)
#pragma unroll
                for (int h = 0; h < 2; h++)
                    smf[O_RED + wn * 128 + gm + mt * 16 + h * 8 + row4] = rmax[mt][h];
        }
        __syncthreads();

        float scale[2][2];
#pragma unroll
        for (int mt = 0; mt < 2; mt++)
#pragma unroll
            for (int h = 0; h < 2; h++) {
                int r = gm + mt * 16 + h * 8 + row4;
                float mtile = fmaxf(smf[O_RED + r], smf[O_RED + 128 + r]);
                float mnew  = fmaxf(m_run[mt][h], mtile);
                scale[mt][h] = __expf(m_run[mt][h] - mnew);
                m_run[mt][h] = mnew;
            }

        // p = exp(s - m), tf32 P -> smem, accumulate row sums
        float rsum[2][2] = {{0.f, 0.f}, {0.f, 0.f}};
#pragma unroll
        for (int mt = 0; mt < 2; mt++)
#pragma unroll
            for (int nt = 0; nt < 8; nt++) {
                float p0 = __expf(acc[mt][nt][0] - m_run[mt][0]);
                float p1 = __expf(acc[mt][nt][1] - m_run[mt][0]);
                float p2 = __expf(acc[mt][nt][2] - m_run[mt][1]);
                float p3 = __expf(acc[mt][nt][3] - m_run[mt][1]);
                rsum[mt][0] += p0 + p1;
                rsum[mt][1] += p2 + p3;
                int cc = gn + nt * 8 + 2 * kq;
                uint2 u0; u0.x = tf32r(p0); u0.y = tf32r(p1);
                uint2 u1; u1.x = tf32r(p2); u1.y = tf32r(p3);
                *(uint2*)&sm[O_PS + (gm + mt * 16 + row4) * 132 + cc] = u0;
                *(uint2*)&sm[O_PS + (gm + mt * 16 + row4 + 8) * 132 + cc] = u1;
            }
#pragma unroll
        for (int mt = 0; mt < 2; mt++)
#pragma unroll
            for (int h = 0; h < 2; h++) {
                rsum[mt][h] += __shfl_xor_sync(0xffffffffu, rsum[mt][h], 1);
                rsum[mt][h] += __shfl_xor_sync(0xffffffffu, rsum[mt][h], 2);
            }
        if (kq == 0) {
#pragma unroll
            for (int mt = 0; mt < 2; mt++)
#pragma unroll
                for (int h = 0; h < 2; h++)
                    smf[O_RED + 256 + wn * 128 + gm + mt * 16 + h * 8 + row4] = rsum[mt][h];
        }

        // rescale O while sums land
#pragma unroll
        for (int mt = 0; mt < 2; mt++)
#pragma unroll
            for (int nt = 0; nt < 4; nt++) {
                Oa[mt][nt][0] *= scale[mt][0];
                Oa[mt][nt][1] *= scale[mt][0];
                Oa[mt][nt][2] *= scale[mt][1];
                Oa[mt][nt][3] *= scale[mt][1];
            }
        __syncthreads();   // P + redsum visible

#pragma unroll
        for (int mt = 0; mt < 2; mt++)
#pragma unroll
            for (int h = 0; h < 2; h++) {
                int r = gm + mt * 16 + h * 8 + row4;
                l_run[mt][h] = l_run[mt][h] * scale[mt][h]
                             + smf[O_RED + 256 + r] + smf[O_RED + 256 + 128 + r];
            }

        // ---- O += P V ----
#pragma unroll
        for (int s2 = 0; s2 < 16; s2++) {
            const int kk = s2 * 8;
            uint32_t a[2][4];
#pragma unroll
            for (int mt = 0; mt < 2; mt++) {
                int rbase = (gm + mt * 16 + row4) * 132;
                a[mt][0] = sm[O_PS + rbase + kk + kq];
                a[mt][1] = sm[O_PS + rbase + 8 * 132 + kk + kq];
                a[mt][2] = sm[O_PS + rbase + kk + kq + 4];
                a[mt][3] = sm[O_PS + rbase + 8 * 132 + kk + kq + 4];
            }
#pragma unroll
            for (int nt = 0; nt < 4; nt++) {
                int nb = (kk + kq) * 68 + gn2 + nt * 8 + row4;
                uint32_t b0 = sm[O_VS + nb];
                uint32_t b1 = sm[O_VS + nb + 4 * 68];
                mma_tf32(Oa[0][nt], a[0], b0, b1);
                mma_tf32(Oa[1][nt], a[1], b0, b1);
            }
        }
    }

    // ---- epilogue: normalize and write ctx [B,S,EMB] ----
    const int b = bh >> 4;
    const int h = bh & 15;
#pragma unroll
    for (int mt = 0; mt < 2; mt++) {
        float inv0 = 1.f / l_run[mt][0];
        float inv1 = 1.f / l_run[mt][1];
        int r0 = q0 + gm + mt * 16 + row4;
#pragma unroll
        for (int nt = 0; nt < 4; nt++) {
            int d = gn2 + nt * 8 + 2 * kq;
            float2 v0, v1;
            v0.x = Oa[mt][nt][0] * inv0; v0.y = Oa[mt][nt][1] * inv0;
            v1.x = Oa[mt][nt][2] * inv1; v1.y = Oa[mt][nt][3] * inv1;
            *(float2*)(g_ctx + ((size_t)(b * S_) + r0) * EMB_ + h * DH_ + d) = v0;
            *(float2*)(g_ctx + ((size_t)(b * S_) + r0 + 8) * EMB_ + h * DH_ + d) = v1;
        }
    }
}

// ---------------------------------------------------------------------------
// Launch
// ---------------------------------------------------------------------------
extern "C" void kernel_launch(void* const* d_in, const int* in_sizes, int n_in,
                              void* d_out, int out_size)
{
    const float* x  = (const float*)d_in[0];
    const float* Wq = (const float*)d_in[1];
    const float* bq = (const float*)d_in[2];
    const float* Wk = (const float*)d_in[3];
    const float* bk = (const float*)d_in[4];
    const float* Wv = (const float*)d_in[5];
    const float* bv = (const float*)d_in[6];
    const float* Wo = (const float*)d_in[7];
    const float* bo = (const float*)d_in[8];
    float* out = (float*)d_out;

    cudaFuncSetAttribute(attn_mma_kernel,
                         cudaFuncAttributeMaxDynamicSharedMemorySize, ATTN_SMEM_BYTES);

    dim3 gQKV(EMB_ / 128, M_ / 128, 3);           // (8, 64, 3)
    qkv_mma_kernel<<<gQKV, 256>>>(x, Wq, bq, Wk, bk, Wv, bv);

    dim3 gAttn(S_ / 128, B_ * H_);                // (16, 64)
    attn_mma_kernel<<<gAttn, 256, ATTN_SMEM_BYTES>>>();

    dim3 gO(EMB_ / 128, M_ / 128);                // (8, 64)
    oproj_mma_kernel<<<gO, 256>>>(Wo, bo, out);
}